// round 1
// baseline (speedup 1.0000x reference)
#include <cuda_runtime.h>
#include <cuda_bf16.h>

// Problem constants: B=8, CIN=COUT=128, H=W=64
#define NB   8
#define NC   128
#define NH   64
#define NW   64

// Scratch (device globals — no allocation allowed)
__device__ __align__(16) float g_xt[NB * NH * NW * NC];   // NHWC transposed input, 16 MB
__device__ __align__(16) float g_off[NB * NH * NW * 4];   // per-pixel: shift_y, shift_x, scale1, scale2
__device__ __align__(16) float g_wt[9 * NC * NC];         // w transposed to [k][c][o]

__constant__ float c_BY[9] = {-1,-1,-1, 0,0,0, 1,1,1};
__constant__ float c_BX[9] = {-1, 0, 1,-1,0,1,-1,0,1};

// ---------------------------------------------------------------------------
// Kernel 1: NCHW -> NHWC transpose of x via 32x32 smem tiles
// grid: (NB*NH, NC/32, NW/32), block: (32,8)
// ---------------------------------------------------------------------------
__global__ void k_transpose(const float* __restrict__ x) {
    __shared__ float tile[32][33];
    int bh = blockIdx.x;
    int b = bh >> 6, h = bh & 63;
    int c0 = blockIdx.y * 32;
    int w0 = blockIdx.z * 32;
    int tx = threadIdx.x, ty = threadIdx.y;
#pragma unroll
    for (int q = 0; q < 4; q++) {
        int c = c0 + ty + 8 * q;
        tile[ty + 8 * q][tx] = x[(((b * NC + c) * NH + h) * NW) + w0 + tx];
    }
    __syncthreads();
#pragma unroll
    for (int q = 0; q < 4; q++) {
        int w = w0 + ty + 8 * q;
        g_xt[((b * NH + h) * NW + w) * NC + c0 + tx] = tile[tx][ty + 8 * q];
    }
}

// ---------------------------------------------------------------------------
// Kernel 2: w[o][c][k] -> g_wt[k][c][o]
// ---------------------------------------------------------------------------
__global__ void k_wt(const float* __restrict__ w) {
    int i = blockIdx.x * 256 + threadIdx.x;
    if (i < 9 * NC * NC) {
        int k = i / (NC * NC);
        int r = i % (NC * NC);
        int c = r >> 7, o = r & 127;
        g_wt[i] = w[(o * NC + c) * 9 + k];
    }
}

// ---------------------------------------------------------------------------
// Kernel 3: offset conv (only channels 0..3 are used by the model).
// Block = one (b,h) output row. Stages 3 input rows (NHWC) + w_off in smem.
// Warp-per-pixel, lanes over channel quads -> conflict-free LDS.128.
// dyn smem: xin 3*64*128 floats + sw 4*9*128 floats
// ---------------------------------------------------------------------------
extern __shared__ float dsm[];
__global__ void __launch_bounds__(256) k_off(const float* __restrict__ w_off,
                                             const float* __restrict__ b_off) {
    float* xin = dsm;                  // [3][64][128]
    float* sw  = dsm + 3 * NW * NC;    // [4][9][128]
    int h = blockIdx.x, b = blockIdx.y;
    int t = threadIdx.x;

    // load 3 rows (zero-padded outside)
    for (int r = 0; r < 3; r++) {
        int hr = h + r - 1;
        float4* dst = (float4*)(xin + r * NW * NC);
        if (hr >= 0 && hr < NH) {
            const float4* src = (const float4*)(g_xt + ((b * NH + hr) * NW) * NC);
            for (int i = t; i < (NW * NC) / 4; i += 256) dst[i] = src[i];
        } else {
            for (int i = t; i < (NW * NC) / 4; i += 256) dst[i] = make_float4(0.f, 0.f, 0.f, 0.f);
        }
    }
    // load w_off transposed to [j][tap][c], j = 0..3 only
    for (int i = t; i < 4 * 9 * NC; i += 256) {
        int j = i / (9 * NC);
        int r2 = i % (9 * NC);
        int tap = r2 >> 7, c = r2 & 127;
        sw[i] = w_off[(j * NC + c) * 9 + tap];
    }
    __syncthreads();

    int wid = t >> 5, lane = t & 31;
    for (int it = 0; it < 8; it++) {
        int p = it * 8 + wid;   // pixel (w coordinate)
        float a0 = 0.f, a1 = 0.f, a2 = 0.f, a3 = 0.f;
#pragma unroll
        for (int tap = 0; tap < 9; tap++) {
            int dx = tap % 3 - 1;
            int dy = tap / 3;        // row index in xin (0..2)
            int xx = p + dx;
            if (xx < 0 || xx >= NW) continue;
            float4 xv = *(const float4*)(xin + (dy * NW + xx) * NC + lane * 4);
            float4 w0 = *(const float4*)(sw + (0 * 9 + tap) * NC + lane * 4);
            float4 w1 = *(const float4*)(sw + (1 * 9 + tap) * NC + lane * 4);
            float4 w2 = *(const float4*)(sw + (2 * 9 + tap) * NC + lane * 4);
            float4 w3 = *(const float4*)(sw + (3 * 9 + tap) * NC + lane * 4);
            a0 += xv.x * w0.x + xv.y * w0.y + xv.z * w0.z + xv.w * w0.w;
            a1 += xv.x * w1.x + xv.y * w1.y + xv.z * w1.z + xv.w * w1.w;
            a2 += xv.x * w2.x + xv.y * w2.y + xv.z * w2.z + xv.w * w2.w;
            a3 += xv.x * w3.x + xv.y * w3.y + xv.z * w3.z + xv.w * w3.w;
        }
#pragma unroll
        for (int off = 16; off; off >>= 1) {
            a0 += __shfl_xor_sync(0xffffffffu, a0, off);
            a1 += __shfl_xor_sync(0xffffffffu, a1, off);
            a2 += __shfl_xor_sync(0xffffffffu, a2, off);
            a3 += __shfl_xor_sync(0xffffffffu, a3, off);
        }
        if (lane == 0) {
            float sy = a0 + b_off[0];
            float sx = a1 + b_off[1];
            float s1 = fmaxf(a2 + b_off[2], 0.f) + 1.f;
            float s2 = fmaxf(a3 + b_off[3], 0.f) + 1.f;
            *(float4*)(g_off + ((b * NH + h) * NW + p) * 4) = make_float4(sy, sx, s1, s2);
        }
    }
}

// ---------------------------------------------------------------------------
// Kernel 4: main deformable conv.
// Block = one (b,h) row: M=64 pixels, N=128 outputs, 256 threads.
// Per tap k: (a) precompute corner idx/weights, (b) warp-per-pixel bilinear
// sample into s_sm[pixel][132] (STS.128 conflict-free), (c) register-blocked
// GEMM: thread = 4 outputs x 8 pixels accumulated as packed f32x2 FMA.
// ---------------------------------------------------------------------------
__global__ void __launch_bounds__(256) k_main(const float* __restrict__ bias,
                                              float* __restrict__ out) {
    __shared__ float s_sm[8448];       // sampling: [64][132]; output stage: [128][66]
    __shared__ float4 cw_sm[64];
    __shared__ int4   ci_sm[64];
    __shared__ float4 par_sm[64];

    int h = blockIdx.x, b = blockIdx.y;
    int t = threadIdx.x;
    int wid = t >> 5, lane = t & 31;
    int oq = t & 31;                   // output quad: o = 4*oq .. 4*oq+3
    int mg = t >> 5;                   // pixel group: m = mg*8 .. mg*8+7

    if (t < 64) par_sm[t] = *(const float4*)(g_off + ((b * NH + h) * NW + t) * 4);

    unsigned long long acc[16];
#pragma unroll
    for (int i = 0; i < 16; i++) acc[i] = 0ull;

    const float* xb = g_xt + b * (NH * NW * NC);
    __syncthreads();

    for (int k = 0; k < 9; k++) {
        // --- corner precompute (one thread per pixel) ---
        if (t < 64) {
            float4 pr = par_sm[t];
            float sc = (k & 1) ? pr.w : pr.z;     // edge taps -> scale2, corner -> scale1 (center: BASE=0)
            float py = (float)h + c_BY[k] * sc + pr.x;
            float px = (float)t + c_BX[k] * sc + pr.y;
            float y0f = floorf(py), x0f = floorf(px);
            float wy = py - y0f, wx = px - x0f;
            int y0 = (int)y0f, x0 = (int)x0f;
            int y1 = y0 + 1, x1 = x0 + 1;
            float w00 = (1.f - wy) * (1.f - wx);
            float w01 = (1.f - wy) * wx;
            float w10 = wy * (1.f - wx);
            float w11 = wy * wx;
            bool vy0 = (y0 >= 0) && (y0 < NH);
            bool vy1 = (y1 >= 0) && (y1 < NH);
            bool vx0 = (x0 >= 0) && (x0 < NW);
            bool vx1 = (x1 >= 0) && (x1 < NW);
            int cy0 = min(max(y0, 0), NH - 1), cy1 = min(max(y1, 0), NH - 1);
            int cx0 = min(max(x0, 0), NW - 1), cx1 = min(max(x1, 0), NW - 1);
            cw_sm[t] = make_float4((vy0 && vx0) ? w00 : 0.f,
                                   (vy0 && vx1) ? w01 : 0.f,
                                   (vy1 && vx0) ? w10 : 0.f,
                                   (vy1 && vx1) ? w11 : 0.f);
            ci_sm[t] = make_int4((cy0 * NW + cx0) * NC, (cy0 * NW + cx1) * NC,
                                 (cy1 * NW + cx0) * NC, (cy1 * NW + cx1) * NC);
        }
        __syncthreads();

        // --- bilinear sampling: warp-per-pixel, lane = channel quad ---
#pragma unroll
        for (int it = 0; it < 8; it++) {
            int p = it * 8 + wid;
            float4 cw = cw_sm[p];
            int4 ci = ci_sm[p];
            float4 v00 = *(const float4*)(xb + ci.x + lane * 4);
            float4 v01 = *(const float4*)(xb + ci.y + lane * 4);
            float4 v10 = *(const float4*)(xb + ci.z + lane * 4);
            float4 v11 = *(const float4*)(xb + ci.w + lane * 4);
            float4 s;
            s.x = cw.x * v00.x + cw.y * v01.x + cw.z * v10.x + cw.w * v11.x;
            s.y = cw.x * v00.y + cw.y * v01.y + cw.z * v10.y + cw.w * v11.y;
            s.z = cw.x * v00.z + cw.y * v01.z + cw.z * v10.z + cw.w * v11.z;
            s.w = cw.x * v00.w + cw.y * v01.w + cw.z * v10.w + cw.w * v11.w;
            *(float4*)(s_sm + p * 132 + lane * 4) = s;
        }
        __syncthreads();

        // --- GEMM accumulate: per c: 1 LDG.128 (w quad) + 8 broadcast LDS + 16 FFMA2 ---
        const float* wk = g_wt + k * (NC * NC) + 4 * oq;
        const float* srow = s_sm + mg * (8 * 132);
#pragma unroll 4
        for (int c = 0; c < NC; c++) {
            ulonglong2 wp = *(const ulonglong2*)(wk + c * NC);
#pragma unroll
            for (int i = 0; i < 8; i++) {
                float s = srow[i * 132 + c];
                unsigned long long ss;
                asm("mov.b64 %0, {%1, %1};" : "=l"(ss) : "f"(s));
                asm("fma.rn.f32x2 %0, %1, %2, %0;" : "+l"(acc[i])     : "l"(wp.x), "l"(ss));
                asm("fma.rn.f32x2 %0, %1, %2, %0;" : "+l"(acc[i + 8]) : "l"(wp.y), "l"(ss));
            }
        }
        __syncthreads();
    }

    // --- stage output tile transposed to [o][66] and write NCHW coalesced ---
#pragma unroll
    for (int i = 0; i < 8; i++) {
        int m = mg * 8 + i;
        float lo, hi;
        asm("mov.b64 {%0, %1}, %2;" : "=f"(lo), "=f"(hi) : "l"(acc[i]));
        s_sm[(4 * oq + 0) * 66 + m] = lo;
        s_sm[(4 * oq + 1) * 66 + m] = hi;
        asm("mov.b64 {%0, %1}, %2;" : "=f"(lo), "=f"(hi) : "l"(acc[i + 8]));
        s_sm[(4 * oq + 2) * 66 + m] = lo;
        s_sm[(4 * oq + 3) * 66 + m] = hi;
    }
    __syncthreads();
    float* ob = out + ((b * NC) * NH + h) * NW;
    for (int idx = t; idx < NC * NW; idx += 256) {
        int o = idx >> 6, m = idx & 63;
        ob[o * (NH * NW) + m] = s_sm[o * 66 + m] + __ldg(bias + o);
    }
}

// ---------------------------------------------------------------------------
extern "C" void kernel_launch(void* const* d_in, const int* in_sizes, int n_in,
                              void* d_out, int out_size) {
    const float* x     = (const float*)d_in[0];
    const float* w_off = (const float*)d_in[1];
    const float* b_off = (const float*)d_in[2];
    const float* w     = (const float*)d_in[3];
    const float* bias  = (const float*)d_in[4];
    float* out = (float*)d_out;

    k_transpose<<<dim3(NB * NH, NC / 32, NW / 32), dim3(32, 8)>>>(x);
    k_wt<<<(9 * NC * NC + 255) / 256, 256>>>(w);

    int off_smem = (3 * NW * NC + 4 * 9 * NC) * (int)sizeof(float);   // 116 KB
    cudaFuncSetAttribute(k_off, cudaFuncAttributeMaxDynamicSharedMemorySize, off_smem);
    k_off<<<dim3(NH, NB), 256, off_smem>>>(w_off, b_off);

    k_main<<<dim3(NH, NB), 256>>>(bias, out);
}